// round 14
// baseline (speedup 1.0000x reference)
#include <cuda_runtime.h>
#include <cuda_bf16.h>
#include <math.h>
#include <stdint.h>

#define RES   4096
#define DD    128
#define NN    256
#define BB    8
#define SS    256
#define VV    50257
#define LL    2
#define WROWS 50304          // 393 * 128, padded vocab rows
#define NTILES 393
#define MTILES 16
#define UNITS  (NTILES * MTILES)   // 6288
#define CHUNKS 444                 // 148 * 3 -> exactly 3 waves

// Constants matching the reference's fp32 casts of python doubles
#define PHIF   ((float)1.6180339887498948482045868343656381177203)
#define STEPF  ((float)(6.2831853071795864769252867665590 / 4096.0))
#define SCALEF ((float)(4096.0 / 6.2831853071795864769252867665590))

// Scratch (no allocation allowed)
__device__ float g_sin[RES];
__device__ float g_cos[RES];
__device__ float g_X[SS * BB * DD];   // rows m = t*8 + b, 128 cols

// Pre-split bf16 hi/lo planes (row-major: row*128 bf16 = 256B rows)
__device__ __align__(16) __nv_bfloat16 g_Wh[WROWS * DD];
__device__ __align__(16) __nv_bfloat16 g_Wl[WROWS * DD];
__device__ __align__(16) __nv_bfloat16 g_Xh[SS * BB * DD];
__device__ __align__(16) __nv_bfloat16 g_Xl[SS * BB * DD];

// ===========================================================================
// Helpers
// ===========================================================================
__device__ __forceinline__ uint32_t smem_u32(const void* p) {
    uint32_t a;
    asm("{ .reg .u64 t; cvta.to.shared.u64 t, %1; cvt.u32.u64 %0, t; }"
        : "=r"(a) : "l"(p));
    return a;
}

__device__ __forceinline__ uint32_t pk(__nv_bfloat16 a, __nv_bfloat16 b) {
    uint16_t ua = *(uint16_t*)&a, ub = *(uint16_t*)&b;
    return (uint32_t)ua | ((uint32_t)ub << 16);
}

#define LDMATRIX_X4(r0, r1, r2, r3, addr)                                     \
    asm volatile("ldmatrix.sync.aligned.m8n8.x4.shared.b16 {%0,%1,%2,%3}, [%4];" \
        : "=r"(r0), "=r"(r1), "=r"(r2), "=r"(r3) : "r"(addr))

#define MMA_BF16(c, a0, a1, a2, a3, b0, b1)                                   \
    asm volatile("mma.sync.aligned.m16n8k16.row.col.f32.bf16.bf16.f32 "       \
        "{%0,%1,%2,%3}, {%4,%5,%6,%7}, {%8,%9}, {%0,%1,%2,%3};"               \
        : "+f"((c)[0]), "+f"((c)[1]), "+f"((c)[2]), "+f"((c)[3])              \
        : "r"(a0), "r"(a1), "r"(a2), "r"(a3), "r"(b0), "r"(b1))

#define CP_ASYNC16(smaddr, gptr)                                              \
    asm volatile("cp.async.cg.shared.global [%0], [%1], 16;"                  \
        :: "r"(smaddr), "l"(gptr))
#define CP_COMMIT() asm volatile("cp.async.commit_group;" ::: "memory")
#define CP_WAIT0()  asm volatile("cp.async.wait_group 0;" ::: "memory")
#define CP_WAIT1()  asm volatile("cp.async.wait_group 1;" ::: "memory")
#define GBAR(id)    asm volatile("bar.sync %0, 256;" :: "r"(id) : "memory")

// ---------------------------------------------------------------------------
// Kernel 0: build sin/cos tables exactly like the reference
// ---------------------------------------------------------------------------
__global__ void k_tables() {
    int i = blockIdx.x * blockDim.x + threadIdx.x;
    if (i < RES) {
        float a = __fmul_rn((float)i, STEPF);
        g_sin[i] = sinf(a);
        g_cos[i] = cosf(a);
    }
}

// ---------------------------------------------------------------------------
// Kernel 1: elementwise recurrence over t (bit-exact path, unchanged)
// ---------------------------------------------------------------------------
__global__ void k_recur(const int* __restrict__ ids,
                        const float* __restrict__ emb,
                        float* __restrict__ out) {
    __shared__ float s_sin[RES];
    __shared__ float s_cos[RES];
    __shared__ int   s_ids[SS];

    int b = blockIdx.x;
    int d = threadIdx.x;   // 128 threads

    for (int i = d; i < RES; i += 128) { s_sin[i] = g_sin[i]; s_cos[i] = g_cos[i]; }
    for (int i = d; i < SS;  i += 128) s_ids[i] = ids[b * SS + i];
    __syncthreads();

    float hr = 0.0f, hi = 0.0f;

    for (int t0 = 0; t0 < SS; t0 += 8) {
        float wv[8], bv[8];
#pragma unroll
        for (int j = 0; j < 8; ++j) {
            const float* e = emb + (size_t)s_ids[t0 + j] * (2 * DD);
            wv[j] = e[d];
            bv[j] = e[DD + d];
        }
#pragma unroll
        for (int j = 0; j < 8; ++j) {
            int   t     = t0 + j;
            float tphi  = __fmul_rn((float)t, PHIF);
            float num   = __fadd_rn(hr, hi);
            float den   = __fadd_rn(1.0f, fabsf(wv[j]));
            float theta = __fadd_rn(__fadd_rn(__fdiv_rn(num, den), bv[j]), tphi);
            int   idx   = __float2int_rn(__fmul_rn(theta, SCALEF)) & (RES - 1);
            hi = s_sin[idx];
            hr = s_cos[idx];
            g_X[(size_t)t * (BB * DD) + b * DD + d] = __fadd_rn(hr, hi);
        }
    }

    size_t base = (size_t)BB * SS * VV;
    out[base + b * DD + d]            = hr;  // h_real
    out[base + BB * DD + b * DD + d]  = hi;  // h_imag
}

// ---------------------------------------------------------------------------
// fp32 -> bf16 hi/lo split of a float4
// ---------------------------------------------------------------------------
__device__ __forceinline__ void split4(float4 v, uint2& hp, uint2& lp) {
    __nv_bfloat16 h0 = __float2bfloat16(v.x);
    __nv_bfloat16 h1 = __float2bfloat16(v.y);
    __nv_bfloat16 h2 = __float2bfloat16(v.z);
    __nv_bfloat16 h3 = __float2bfloat16(v.w);
    __nv_bfloat16 l0 = __float2bfloat16(v.x - __bfloat162float(h0));
    __nv_bfloat16 l1 = __float2bfloat16(v.y - __bfloat162float(h1));
    __nv_bfloat16 l2 = __float2bfloat16(v.z - __bfloat162float(h2));
    __nv_bfloat16 l3 = __float2bfloat16(v.w - __bfloat162float(h3));
    hp = make_uint2(pk(h0, h1), pk(h2, h3));
    lp = make_uint2(pk(l0, l1), pk(l2, l3));
}

// ---------------------------------------------------------------------------
// Kernel 2: the two MLP layers — EXACT R10 78us version (tables + weight
// tiles in smem, 256 threads, grid 256). Only change: epilogue writes the
// bf16 hi/lo X planes directly (k_split_x deleted).
// ---------------------------------------------------------------------------
__global__ void k_layers(const float* __restrict__ W,
                         const float* __restrict__ bias,
                         const float* __restrict__ Wr,
                         const float* __restrict__ Wi) {
    extern __shared__ float sm[];
    float* s_sin = sm;                  // 4096
    float* s_cos = s_sin + RES;         // 4096
    float* s_x   = s_cos + RES;         // 1024  (8 x 128)
    float* s_cs  = s_x + BB * DD;       // 2048  (8 x 256)
    float* s_sn  = s_cs + BB * NN;      // 2048
    float* s_wr  = s_sn + BB * NN;      // 128*36
    float* s_wi  = s_wr + DD * 36;      // 128*36

    int tid = threadIdx.x;
    int t   = blockIdx.x;

    for (int i = tid; i < RES; i += 256) { s_sin[i] = g_sin[i]; s_cos[i] = g_cos[i]; }
    float* gx = g_X + (size_t)t * (BB * DD);
    for (int i = tid; i < BB * DD; i += 256) s_x[i] = gx[i];
    __syncthreads();

    float tphi = __fmul_rn((float)t, PHIF);
    int n    = tid;
    int dcol = tid & 127;
    int bhi  = tid >> 7;   // 0 or 1

    for (int layer = 0; layer < LL; ++layer) {
        const float4* Wn = (const float4*)(W + ((size_t)layer * NN + n) * DD);
        const float4* x4 = (const float4*)s_x;
        float acc[8];
#pragma unroll
        for (int bb = 0; bb < 8; ++bb) acc[bb] = 0.0f;
#pragma unroll 8
        for (int q = 0; q < 32; ++q) {
            float4 w = Wn[q];
#pragma unroll
            for (int bb = 0; bb < 8; ++bb) {
                float4 xv = x4[bb * 32 + q];
                acc[bb] += w.x * xv.x + w.y * xv.y + w.z * xv.z + w.w * xv.w;
            }
        }
        float bsn = bias[layer * NN + n];
#pragma unroll
        for (int bb = 0; bb < 8; ++bb) {
            float th  = acc[bb] + bsn + tphi;
            int   idx = __float2int_rn(__fmul_rn(th, SCALEF)) & (RES - 1);
            s_sn[bb * NN + n] = s_sin[idx];
            s_cs[bb * NN + n] = s_cos[idx];
        }
        __syncthreads();

        float o[4] = {0.0f, 0.0f, 0.0f, 0.0f};
        const float* WrL = Wr + (size_t)layer * DD * NN;
        const float* WiL = Wi + (size_t)layer * DD * NN;
        for (int n0 = 0; n0 < NN; n0 += 32) {
#pragma unroll
            for (int l2 = 0; l2 < 16; ++l2) {
                int f  = tid + 256 * l2;   // 0..4095
                int dd = f >> 5, nn2 = f & 31;
                s_wr[dd * 36 + nn2] = WrL[dd * NN + n0 + nn2];
                s_wi[dd * 36 + nn2] = WiL[dd * NN + n0 + nn2];
            }
            __syncthreads();
            const float4* wr4 = (const float4*)(s_wr + dcol * 36);
            const float4* wi4 = (const float4*)(s_wi + dcol * 36);
#pragma unroll
            for (int q = 0; q < 8; ++q) {
                float4 wr = wr4[q];
                float4 wi = wi4[q];
#pragma unroll
                for (int p = 0; p < 4; ++p) {
                    int bb = bhi + 2 * p;
                    float4 cs = ((const float4*)(s_cs + bb * NN + n0))[q];
                    float4 sn = ((const float4*)(s_sn + bb * NN + n0))[q];
                    o[p] += cs.x * wr.x + cs.y * wr.y + cs.z * wr.z + cs.w * wr.w
                          + sn.x * wi.x + sn.y * wi.y + sn.z * wi.z + sn.w * wi.w;
                }
            }
            __syncthreads();
        }
#pragma unroll
        for (int p = 0; p < 4; ++p) {
            int bb = bhi + 2 * p;
            float ov = o[p];
            float sv = ov / (1.0f + expf(-ov));   // o * sigmoid(o)
            s_x[bb * DD + dcol] += sv;
        }
        __syncthreads();
    }

    // ---- epilogue: write bf16 hi/lo planes of final x (split fused) ----
    {
        float4 v = ((const float4*)s_x)[tid];     // 256 float4 = 1024 floats
        uint2 hp, lp;
        split4(v, hp, lp);
        ((uint2*)g_Xh)[(size_t)t * 256 + tid] = hp;
        ((uint2*)g_Xl)[(size_t)t * 256 + tid] = lp;
    }
}

// ---------------------------------------------------------------------------
// Split kernel for out_w: fp32 -> bf16 hi/lo planes (row-major)
// ---------------------------------------------------------------------------
__global__ void k_split_w(const float* __restrict__ Wv) {
    int f = blockIdx.x * blockDim.x + threadIdx.x;   // 0 .. WROWS*32-1
    int r = f >> 5, kq = f & 31;
    float4 v = make_float4(0.f, 0.f, 0.f, 0.f);
    if (r < VV) v = ((const float4*)Wv)[(size_t)r * 32 + kq];
    uint2 hp, lp;
    split4(v, hp, lp);
    ((uint2*)g_Wh)[f] = hp;
    ((uint2*)g_Wl)[f] = lp;
}

// ---------------------------------------------------------------------------
// Kernel 3: work-list logits GEMM with TWO independent 8-warp groups.
//   Identical structure to the 409.6us version; ONLY change: software-
//   pipelined fragment loads — per k16, all LDSMs (cur bL/aL + next aH/bH)
//   are issued BEFORE the 24 MMAs, so no load sits adjacent to its consumer.
// smem: BH 32K | BL 32K | G0A0 32K | G0A1 32K | G1A0 32K | G1A1 32K = 192K
// ---------------------------------------------------------------------------
#define PB_BH 0u
#define PB_BL 32768u
#define PB_A  65536u
#define SMEM_PIPE 196608u

__device__ __forceinline__ void issue_B(uint32_t sb, int nt, int tid) {
    const char* gWh = (const char*)g_Wh;
    const char* gWl = (const char*)g_Wl;
#pragma unroll
    for (int i = 0; i < 4; ++i) {
        int f = tid + 512 * i;            // 0..2047
        int r = f >> 4, u = f & 15;
        uint32_t so = (uint32_t)(r * 256 + ((u ^ (r & 7)) << 4));
        size_t   go = (size_t)(nt * 128 + r) * 256 + u * 16;
        CP_ASYNC16(sb + PB_BH + so, gWh + go);
        CP_ASYNC16(sb + PB_BL + so, gWl + go);
    }
}

// Load 64 rows (this group's half of an M-tile) into a 32KB buffer.
__device__ __forceinline__ void issue_Ag(uint32_t abuf, int mt, int grp, int gtid) {
    const char* gXh = (const char*)g_Xh;
    const char* gXl = (const char*)g_Xl;
#pragma unroll
    for (int i = 0; i < 4; ++i) {
        int f = gtid + 256 * i;           // 0..1023
        int r = f >> 4, u = f & 15;       // r: 0..63
        uint32_t so = (uint32_t)(r * 256 + ((u ^ (r & 7)) << 4));
        size_t   go = (size_t)(mt * 128 + grp * 64 + r) * 256 + u * 16;
        CP_ASYNC16(abuf + so, gXh + go);
        CP_ASYNC16(abuf + 16384u + so, gXl + go);
    }
}

__global__ void __launch_bounds__(512, 1)
k_logits_wg(float* __restrict__ out) {
    extern __shared__ char smc[];
    uint32_t sb = smem_u32(smc);

    int tid  = threadIdx.x;
    int lane = tid & 31;
    int wid  = tid >> 5;
    int grp  = wid >> 3;           // 0 or 1
    int gwid = wid & 7;            // warp within group
    int gtid = tid & 255;
    int bar  = 1 + grp;
    int cid  = blockIdx.x;

    int start = (cid * UNITS) / CHUNKS;
    int end   = ((cid + 1) * UNITS) / CHUNKS;

    int wm = gwid & 1;             // M offset within 64-row half: 0/32
    int wn = gwid >> 1;            // N offset: 0/32/64/96
    int g  = lane >> 3;
    int l7 = lane & 7;
    int ra = l7 + (g & 1) * 8;
    int ua = g >> 1;
    int rb = l7 + (g >> 1) * 8;
    int ub = g & 1;

    // A buffer bases for this group (hi plane; lo at +16384)
    uint32_t abuf0 = sb + PB_A + (uint32_t)grp * 65536u;
    uint32_t abuf1 = abuf0 + 32768u;

    uint32_t arel[2];
#pragma unroll
    for (int mf = 0; mf < 2; ++mf)
        arel[mf] = (uint32_t)((wm * 32 + mf * 16 + ra) * 256);
    uint32_t brow[2];
#pragma unroll
    for (int nf2 = 0; nf2 < 2; ++nf2)
        brow[nf2] = sb + PB_BH + (uint32_t)((wn * 32 + nf2 * 16 + rb) * 256);

    int u = start;
    int cur_nt = u >> 4;
    issue_B(sb, cur_nt, tid);
    issue_Ag(abuf0, u & 15, grp, gtid);
    CP_COMMIT();
    int parity = 0;
    bool freshB = true;

    while (u < end) {
        int nxt = u + 1;
        bool havenext = (nxt < end);
        bool samen = havenext && ((nxt >> 4) == cur_nt);
        if (samen) {
            issue_Ag(parity ? abuf0 : abuf1, nxt & 15, grp, gtid);
            CP_COMMIT();
            CP_WAIT1();
        } else {
            CP_WAIT0();
        }
        if (freshB) { __syncthreads(); freshB = false; }
        else        { GBAR(bar); }

        uint32_t abase = parity ? abuf1 : abuf0;

        float acc[2][4][4];
#pragma unroll
        for (int i = 0; i < 2; ++i)
#pragma unroll
            for (int j = 0; j < 4; ++j)
#pragma unroll
                for (int q = 0; q < 4; ++q) acc[i][j][q] = 0.0f;

        // ---- software-pipelined fragment loads across k16 ----
        uint32_t aH[2][4], bH[2][4];
        {
            uint32_t uxa0 = (uint32_t)((ua ^ l7) << 4);
            uint32_t uxb0 = (uint32_t)((ub ^ l7) << 4);
#pragma unroll
            for (int mf = 0; mf < 2; ++mf)
                LDMATRIX_X4(aH[mf][0], aH[mf][1], aH[mf][2], aH[mf][3],
                            abase + arel[mf] + uxa0);
#pragma unroll
            for (int nf2 = 0; nf2 < 2; ++nf2)
                LDMATRIX_X4(bH[nf2][0], bH[nf2][1], bH[nf2][2], bH[nf2][3],
                            brow[nf2] + uxb0);
        }

#pragma unroll
        for (int k16 = 0; k16 < 8; ++k16) {
            uint32_t uxa = (uint32_t)(((2 * k16 + ua) ^ l7) << 4);
            uint32_t uxb = (uint32_t)(((2 * k16 + ub) ^ l7) << 4);

            // issue ALL loads for this k16 (bL, aL) and the next k16 (aH, bH)
            uint32_t bL[2][4], aL[2][4];
#pragma unroll
            for (int nf2 = 0; nf2 < 2; ++nf2)
                LDMATRIX_X4(bL[nf2][0], bL[nf2][1], bL[nf2][2], bL[nf2][3],
                            brow[nf2] + 32768u + uxb);
#pragma unroll
            for (int mf = 0; mf < 2; ++mf)
                LDMATRIX_X4(aL[mf][0], aL[mf][1], aL[mf][2], aL[mf][3],
                            abase + 16384u + arel[mf] + uxa);

            uint32_t aHn[2][4], bHn[2][4];
            if (k16 < 7) {
                uint32_t uxa1 = (uint32_t)(((2 * (k16 + 1) + ua) ^ l7) << 4);
                uint32_t uxb1 = (uint32_t)(((2 * (k16 + 1) + ub) ^ l7) << 4);
#pragma unroll
                for (int mf = 0; mf < 2; ++mf)
                    LDMATRIX_X4(aHn[mf][0], aHn[mf][1], aHn[mf][2], aHn[mf][3],
                                abase + arel[mf] + uxa1);
#pragma unroll
                for (int nf2 = 0; nf2 < 2; ++nf2)
                    LDMATRIX_X4(bHn[nf2][0], bHn[nf2][1], bHn[nf2][2], bHn[nf2][3],
                                brow[nf2] + uxb1);
            }

            // Term 1: Ah * Bh
#pragma unroll
            for (int mf = 0; mf < 2; ++mf)
#pragma unroll
                for (int nf = 0; nf < 4; ++nf)
                    MMA_BF16(acc[mf][nf], aH[mf][0], aH[mf][1], aH[mf][2], aH[mf][3],
                             bH[nf >> 1][(nf & 1) * 2], bH[nf >> 1][(nf & 1) * 2 + 1]);

            // Term 2: Ah * Bl
#pragma unroll
            for (int mf = 0; mf < 2; ++mf)
#pragma unroll
                for (int nf = 0; nf < 4; ++nf)
                    MMA_BF16(acc[mf][nf], aH[mf][0], aH[mf][1], aH[mf][2], aH[mf][3],
                             bL[nf >> 1][(nf & 1) * 2], bL[nf >> 1][(nf & 1) * 2 + 1]);

            // Term 3: Al * Bh
#pragma unroll
            for (int mf = 0; mf < 2; ++mf)
#pragma unroll
                for (int nf = 0; nf < 4; ++nf)
                    MMA_BF16(acc[mf][nf], aL[mf][0], aL[mf][1], aL[mf][2], aL[mf][3],
                             bH[nf >> 1][(nf & 1) * 2], bH[nf >> 1][(nf & 1) * 2 + 1]);

            // rotate next->cur (full unroll: pure register renaming)
            if (k16 < 7) {
#pragma unroll
                for (int mf = 0; mf < 2; ++mf)
#pragma unroll
                    for (int q = 0; q < 4; ++q) aH[mf][q] = aHn[mf][q];
#pragma unroll
                for (int nf2 = 0; nf2 < 2; ++nf2)
#pragma unroll
                    for (int q = 0; q < 4; ++q) bH[nf2][q] = bHn[nf2][q];
            }
        }

        // ---- epilogue: write into (B,S,V) layout ----
        {
            int mt = u & 15;
            bool fullT = (cur_nt != NTILES - 1);
            int m0 = mt * 128 + grp * 64;
            int cbase = cur_nt * 128 + wn * 32 + (lane & 3) * 2;
#pragma unroll
            for (int mf = 0; mf < 2; ++mf) {
                int rr = m0 + wm * 32 + mf * 16 + (lane >> 2);
#pragma unroll
                for (int half = 0; half < 2; ++half) {
                    int m = rr + half * 8;
                    float* orow = out + (size_t)(m & 7) * SS * VV + (size_t)(m >> 3) * VV;
#pragma unroll
                    for (int nf = 0; nf < 4; ++nf) {
                        int c = cbase + nf * 8;
                        float v0 = acc[mf][nf][half * 2 + 0];
                        float v1 = acc[mf][nf][half * 2 + 1];
                        if (fullT) {
                            orow[c]     = v0;
                            orow[c + 1] = v1;
                        } else {
                            if (c < VV)     orow[c]     = v0;
                            if (c + 1 < VV) orow[c + 1] = v1;
                        }
                    }
                }
            }
        }

        if (havenext && !samen) {
            // nt boundary: all warps (both groups) must be done with B
            __syncthreads();
            cur_nt = nxt >> 4;
            issue_B(sb, cur_nt, tid);
            issue_Ag(parity ? abuf0 : abuf1, nxt & 15, grp, gtid);
            CP_COMMIT();
            freshB = true;
        } else {
            GBAR(bar);   // group's A buffer safe to refill next iteration
        }
        parity ^= 1;
        u = nxt;
    }
}

// ---------------------------------------------------------------------------
extern "C" void kernel_launch(void* const* d_in, const int* in_sizes, int n_in,
                              void* d_out, int out_size) {
    const int*   input_ids = (const int*)  d_in[0];
    const float* emb       = (const float*)d_in[1];
    const float* layer_W   = (const float*)d_in[2];
    const float* layer_b   = (const float*)d_in[3];
    const float* layer_Wr  = (const float*)d_in[4];
    const float* layer_Wi  = (const float*)d_in[5];
    const float* out_w     = (const float*)d_in[6];
    float* out = (float*)d_out;

    const int smem_layers = (2 * RES + BB * DD + 2 * BB * NN + 2 * DD * 36) * sizeof(float);
    cudaFuncSetAttribute(k_layers,    cudaFuncAttributeMaxDynamicSharedMemorySize, smem_layers);
    cudaFuncSetAttribute(k_logits_wg, cudaFuncAttributeMaxDynamicSharedMemorySize, (int)SMEM_PIPE);

    k_tables<<<(RES + 255) / 256, 256>>>();
    k_recur<<<BB, DD>>>(input_ids, emb, out);
    k_split_w<<<(WROWS * 32) / 256, 256>>>(out_w);   // independent of recur/layers
    k_layers<<<SS, 256, smem_layers>>>(layer_W, layer_b, layer_Wr, layer_Wi);

    k_logits_wg<<<CHUNKS, 512, SMEM_PIPE>>>(out);
}

// round 15
// speedup vs baseline: 1.1168x; 1.1168x over previous
#include <cuda_runtime.h>
#include <cuda_bf16.h>
#include <math.h>
#include <stdint.h>

#define RES   4096
#define DD    128
#define NN    256
#define BB    8
#define SS    256
#define VV    50257
#define LL    2
#define WROWS 50304          // 393 * 128, padded vocab rows
#define NTILES 393
#define MTILES 16
#define UNITS  (NTILES * MTILES)   // 6288
#define CHUNKS 444                 // 148 * 3 -> exactly 3 waves
#define SPLITW_BLOCKS 1184

// Constants matching the reference's fp32 casts of python doubles
#define PHIF   ((float)1.6180339887498948482045868343656381177203)
#define STEPF  ((float)(6.2831853071795864769252867665590 / 4096.0))
#define SCALEF ((float)(4096.0 / 6.2831853071795864769252867665590))

// Scratch (no allocation allowed)
__device__ float g_sin[RES];
__device__ float g_cos[RES];
__device__ float g_X[SS * BB * DD];   // rows m = t*8 + b, 128 cols

// Pre-split bf16 hi/lo planes (row-major: row*128 bf16 = 256B rows)
__device__ __align__(16) __nv_bfloat16 g_Wh[WROWS * DD];
__device__ __align__(16) __nv_bfloat16 g_Wl[WROWS * DD];
__device__ __align__(16) __nv_bfloat16 g_Xh[SS * BB * DD];
__device__ __align__(16) __nv_bfloat16 g_Xl[SS * BB * DD];

// ===========================================================================
// Helpers
// ===========================================================================
__device__ __forceinline__ uint32_t smem_u32(const void* p) {
    uint32_t a;
    asm("{ .reg .u64 t; cvta.to.shared.u64 t, %1; cvt.u32.u64 %0, t; }"
        : "=r"(a) : "l"(p));
    return a;
}

__device__ __forceinline__ uint32_t pk(__nv_bfloat16 a, __nv_bfloat16 b) {
    uint16_t ua = *(uint16_t*)&a, ub = *(uint16_t*)&b;
    return (uint32_t)ua | ((uint32_t)ub << 16);
}

#define LDMATRIX_X4(r0, r1, r2, r3, addr)                                     \
    asm volatile("ldmatrix.sync.aligned.m8n8.x4.shared.b16 {%0,%1,%2,%3}, [%4];" \
        : "=r"(r0), "=r"(r1), "=r"(r2), "=r"(r3) : "r"(addr))

#define MMA_BF16(c, a0, a1, a2, a3, b0, b1)                                   \
    asm volatile("mma.sync.aligned.m16n8k16.row.col.f32.bf16.bf16.f32 "       \
        "{%0,%1,%2,%3}, {%4,%5,%6,%7}, {%8,%9}, {%0,%1,%2,%3};"               \
        : "+f"((c)[0]), "+f"((c)[1]), "+f"((c)[2]), "+f"((c)[3])              \
        : "r"(a0), "r"(a1), "r"(a2), "r"(a3), "r"(b0), "r"(b1))

#define CP_ASYNC16(smaddr, gptr)                                              \
    asm volatile("cp.async.cg.shared.global [%0], [%1], 16;"                  \
        :: "r"(smaddr), "l"(gptr))
#define CP_COMMIT() asm volatile("cp.async.commit_group;" ::: "memory")
#define CP_WAIT0()  asm volatile("cp.async.wait_group 0;" ::: "memory")
#define CP_WAIT1()  asm volatile("cp.async.wait_group 1;" ::: "memory")
#define GBAR(id)    asm volatile("bar.sync %0, 256;" :: "r"(id) : "memory")

// ---------------------------------------------------------------------------
// fp32 -> bf16 hi/lo split of a float4
// ---------------------------------------------------------------------------
__device__ __forceinline__ void split4(float4 v, uint2& hp, uint2& lp) {
    __nv_bfloat16 h0 = __float2bfloat16(v.x);
    __nv_bfloat16 h1 = __float2bfloat16(v.y);
    __nv_bfloat16 h2 = __float2bfloat16(v.z);
    __nv_bfloat16 h3 = __float2bfloat16(v.w);
    __nv_bfloat16 l0 = __float2bfloat16(v.x - __bfloat162float(h0));
    __nv_bfloat16 l1 = __float2bfloat16(v.y - __bfloat162float(h1));
    __nv_bfloat16 l2 = __float2bfloat16(v.z - __bfloat162float(h2));
    __nv_bfloat16 l3 = __float2bfloat16(v.w - __bfloat162float(h3));
    hp = make_uint2(pk(h0, h1), pk(h2, h3));
    lp = make_uint2(pk(l0, l1), pk(l2, l3));
}

// ---------------------------------------------------------------------------
// Kernel 1 (mega-prologue): blocks 0-7 = recurrence (local tables);
// blocks 8-23 = write g_sin/g_cos for k_layers; blocks 24+ = out_w split.
// The split's DRAM traffic runs on the 140 SMs idle during the recurrence.
// ---------------------------------------------------------------------------
__global__ void k_pre(const int* __restrict__ ids,
                      const float* __restrict__ emb,
                      float* __restrict__ out,
                      const float* __restrict__ Wv) {
    __shared__ float s_sin[RES];
    __shared__ float s_cos[RES];
    __shared__ int   s_ids[SS];

    int bid = blockIdx.x;
    int d   = threadIdx.x;   // 128 threads

    if (bid >= 24) {
        // ---- out_w fp32 -> bf16 hi/lo split (strided fat blocks) ----
        int total = WROWS * 32;
        for (int f = (bid - 24) * 128 + d; f < total; f += SPLITW_BLOCKS * 128) {
            int r = f >> 5, kq = f & 31;
            float4 v = make_float4(0.f, 0.f, 0.f, 0.f);
            if (r < VV) v = ((const float4*)Wv)[(size_t)r * 32 + kq];
            uint2 hp, lp;
            split4(v, hp, lp);
            ((uint2*)g_Wh)[f] = hp;
            ((uint2*)g_Wl)[f] = lp;
        }
        return;
    }
    if (bid >= 8) {
        // ---- write global sin/cos tables for k_layers ----
        int i0 = (bid - 8) * 256;
        for (int j = d; j < 256; j += 128) {
            int i = i0 + j;
            float a = __fmul_rn((float)i, STEPF);
            g_sin[i] = sinf(a);
            g_cos[i] = cosf(a);
        }
        return;
    }

    // ---- recurrence for batch row b = bid (bit-exact path) ----
    int b = bid;
    for (int i = d; i < RES; i += 128) {
        float a = __fmul_rn((float)i, STEPF);   // identical to k_tables formula
        s_sin[i] = sinf(a);
        s_cos[i] = cosf(a);
    }
    for (int i = d; i < SS; i += 128) s_ids[i] = ids[b * SS + i];
    __syncthreads();

    float hr = 0.0f, hi = 0.0f;

    for (int t0 = 0; t0 < SS; t0 += 8) {
        float wv[8], bv[8];
#pragma unroll
        for (int j = 0; j < 8; ++j) {
            const float* e = emb + (size_t)s_ids[t0 + j] * (2 * DD);
            wv[j] = e[d];
            bv[j] = e[DD + d];
        }
#pragma unroll
        for (int j = 0; j < 8; ++j) {
            int   t     = t0 + j;
            float tphi  = __fmul_rn((float)t, PHIF);
            float num   = __fadd_rn(hr, hi);
            float den   = __fadd_rn(1.0f, fabsf(wv[j]));
            float theta = __fadd_rn(__fadd_rn(__fdiv_rn(num, den), bv[j]), tphi);
            int   idx   = __float2int_rn(__fmul_rn(theta, SCALEF)) & (RES - 1);
            hi = s_sin[idx];
            hr = s_cos[idx];
            g_X[(size_t)t * (BB * DD) + b * DD + d] = __fadd_rn(hr, hi);
        }
    }

    size_t base = (size_t)BB * SS * VV;
    out[base + b * DD + d]            = hr;  // h_real
    out[base + BB * DD + b * DD + d]  = hi;  // h_imag
}

// ---------------------------------------------------------------------------
// Kernel 2: the two MLP layers — EXACT measured-78us version (tables + weight
// tiles in smem, 256 threads, grid 256), epilogue writes bf16 hi/lo X planes.
// ---------------------------------------------------------------------------
__global__ void k_layers(const float* __restrict__ W,
                         const float* __restrict__ bias,
                         const float* __restrict__ Wr,
                         const float* __restrict__ Wi) {
    extern __shared__ float sm[];
    float* s_sin = sm;                  // 4096
    float* s_cos = s_sin + RES;         // 4096
    float* s_x   = s_cos + RES;         // 1024  (8 x 128)
    float* s_cs  = s_x + BB * DD;       // 2048  (8 x 256)
    float* s_sn  = s_cs + BB * NN;      // 2048
    float* s_wr  = s_sn + BB * NN;      // 128*36
    float* s_wi  = s_wr + DD * 36;      // 128*36

    int tid = threadIdx.x;
    int t   = blockIdx.x;

    for (int i = tid; i < RES; i += 256) { s_sin[i] = g_sin[i]; s_cos[i] = g_cos[i]; }
    float* gx = g_X + (size_t)t * (BB * DD);
    for (int i = tid; i < BB * DD; i += 256) s_x[i] = gx[i];
    __syncthreads();

    float tphi = __fmul_rn((float)t, PHIF);
    int n    = tid;
    int dcol = tid & 127;
    int bhi  = tid >> 7;   // 0 or 1

    for (int layer = 0; layer < LL; ++layer) {
        const float4* Wn = (const float4*)(W + ((size_t)layer * NN + n) * DD);
        const float4* x4 = (const float4*)s_x;
        float acc[8];
#pragma unroll
        for (int bb = 0; bb < 8; ++bb) acc[bb] = 0.0f;
#pragma unroll 8
        for (int q = 0; q < 32; ++q) {
            float4 w = Wn[q];
#pragma unroll
            for (int bb = 0; bb < 8; ++bb) {
                float4 xv = x4[bb * 32 + q];
                acc[bb] += w.x * xv.x + w.y * xv.y + w.z * xv.z + w.w * xv.w;
            }
        }
        float bsn = bias[layer * NN + n];
#pragma unroll
        for (int bb = 0; bb < 8; ++bb) {
            float th  = acc[bb] + bsn + tphi;
            int   idx = __float2int_rn(__fmul_rn(th, SCALEF)) & (RES - 1);
            s_sn[bb * NN + n] = s_sin[idx];
            s_cs[bb * NN + n] = s_cos[idx];
        }
        __syncthreads();

        float o[4] = {0.0f, 0.0f, 0.0f, 0.0f};
        const float* WrL = Wr + (size_t)layer * DD * NN;
        const float* WiL = Wi + (size_t)layer * DD * NN;
        for (int n0 = 0; n0 < NN; n0 += 32) {
#pragma unroll
            for (int l2 = 0; l2 < 16; ++l2) {
                int f  = tid + 256 * l2;   // 0..4095
                int dd = f >> 5, nn2 = f & 31;
                s_wr[dd * 36 + nn2] = WrL[dd * NN + n0 + nn2];
                s_wi[dd * 36 + nn2] = WiL[dd * NN + n0 + nn2];
            }
            __syncthreads();
            const float4* wr4 = (const float4*)(s_wr + dcol * 36);
            const float4* wi4 = (const float4*)(s_wi + dcol * 36);
#pragma unroll
            for (int q = 0; q < 8; ++q) {
                float4 wr = wr4[q];
                float4 wi = wi4[q];
#pragma unroll
                for (int p = 0; p < 4; ++p) {
                    int bb = bhi + 2 * p;
                    float4 cs = ((const float4*)(s_cs + bb * NN + n0))[q];
                    float4 sn = ((const float4*)(s_sn + bb * NN + n0))[q];
                    o[p] += cs.x * wr.x + cs.y * wr.y + cs.z * wr.z + cs.w * wr.w
                          + sn.x * wi.x + sn.y * wi.y + sn.z * wi.z + sn.w * wi.w;
                }
            }
            __syncthreads();
        }
#pragma unroll
        for (int p = 0; p < 4; ++p) {
            int bb = bhi + 2 * p;
            float ov = o[p];
            float sv = ov / (1.0f + expf(-ov));   // o * sigmoid(o)
            s_x[bb * DD + dcol] += sv;
        }
        __syncthreads();
    }

    // ---- epilogue: write bf16 hi/lo planes of final x (split fused) ----
    {
        float4 v = ((const float4*)s_x)[tid];     // 256 float4 = 1024 floats
        uint2 hp, lp;
        split4(v, hp, lp);
        ((uint2*)g_Xh)[(size_t)t * 256 + tid] = hp;
        ((uint2*)g_Xl)[(size_t)t * 256 + tid] = lp;
    }
}

// ---------------------------------------------------------------------------
// Kernel 3: work-list logits GEMM with TWO independent 8-warp groups.
//   EXACT byte-identical copy of the 409.6us-measured version. Do not touch.
// smem: BH 32K | BL 32K | G0A0 32K | G0A1 32K | G1A0 32K | G1A1 32K = 192K
// ---------------------------------------------------------------------------
#define PB_BH 0u
#define PB_BL 32768u
#define PB_A  65536u
#define SMEM_PIPE 196608u

__device__ __forceinline__ void issue_B(uint32_t sb, int nt, int tid) {
    const char* gWh = (const char*)g_Wh;
    const char* gWl = (const char*)g_Wl;
#pragma unroll
    for (int i = 0; i < 4; ++i) {
        int f = tid + 512 * i;            // 0..2047
        int r = f >> 4, u = f & 15;
        uint32_t so = (uint32_t)(r * 256 + ((u ^ (r & 7)) << 4));
        size_t   go = (size_t)(nt * 128 + r) * 256 + u * 16;
        CP_ASYNC16(sb + PB_BH + so, gWh + go);
        CP_ASYNC16(sb + PB_BL + so, gWl + go);
    }
}

// Load 64 rows (this group's half of an M-tile) into a 32KB buffer.
__device__ __forceinline__ void issue_Ag(uint32_t abuf, int mt, int grp, int gtid) {
    const char* gXh = (const char*)g_Xh;
    const char* gXl = (const char*)g_Xl;
#pragma unroll
    for (int i = 0; i < 4; ++i) {
        int f = gtid + 256 * i;           // 0..1023
        int r = f >> 4, u = f & 15;       // r: 0..63
        uint32_t so = (uint32_t)(r * 256 + ((u ^ (r & 7)) << 4));
        size_t   go = (size_t)(mt * 128 + grp * 64 + r) * 256 + u * 16;
        CP_ASYNC16(abuf + so, gXh + go);
        CP_ASYNC16(abuf + 16384u + so, gXl + go);
    }
}

__global__ void __launch_bounds__(512, 1)
k_logits_wg(float* __restrict__ out) {
    extern __shared__ char smc[];
    uint32_t sb = smem_u32(smc);

    int tid  = threadIdx.x;
    int lane = tid & 31;
    int wid  = tid >> 5;
    int grp  = wid >> 3;           // 0 or 1
    int gwid = wid & 7;            // warp within group
    int gtid = tid & 255;
    int bar  = 1 + grp;
    int cid  = blockIdx.x;

    int start = (cid * UNITS) / CHUNKS;
    int end   = ((cid + 1) * UNITS) / CHUNKS;

    int wm = gwid & 1;             // M offset within 64-row half: 0/32
    int wn = gwid >> 1;            // N offset: 0/32/64/96
    int g  = lane >> 3;
    int l7 = lane & 7;
    int ra = l7 + (g & 1) * 8;
    int ua = g >> 1;
    int rb = l7 + (g >> 1) * 8;
    int ub = g & 1;

    // A buffer bases for this group (hi plane; lo at +16384)
    uint32_t abuf0 = sb + PB_A + (uint32_t)grp * 65536u;
    uint32_t abuf1 = abuf0 + 32768u;

    uint32_t arel[2];
#pragma unroll
    for (int mf = 0; mf < 2; ++mf)
        arel[mf] = (uint32_t)((wm * 32 + mf * 16 + ra) * 256);
    uint32_t brow[2];
#pragma unroll
    for (int nf2 = 0; nf2 < 2; ++nf2)
        brow[nf2] = sb + PB_BH + (uint32_t)((wn * 32 + nf2 * 16 + rb) * 256);

    int u = start;
    int cur_nt = u >> 4;
    issue_B(sb, cur_nt, tid);
    issue_Ag(abuf0, u & 15, grp, gtid);
    CP_COMMIT();
    int parity = 0;
    bool freshB = true;

    while (u < end) {
        int nxt = u + 1;
        bool havenext = (nxt < end);
        bool samen = havenext && ((nxt >> 4) == cur_nt);
        if (samen) {
            issue_Ag(parity ? abuf0 : abuf1, nxt & 15, grp, gtid);
            CP_COMMIT();
            CP_WAIT1();
        } else {
            CP_WAIT0();
        }
        if (freshB) { __syncthreads(); freshB = false; }
        else        { GBAR(bar); }

        uint32_t abase = parity ? abuf1 : abuf0;

        float acc[2][4][4];
#pragma unroll
        for (int i = 0; i < 2; ++i)
#pragma unroll
            for (int j = 0; j < 4; ++j)
#pragma unroll
                for (int q = 0; q < 4; ++q) acc[i][j][q] = 0.0f;

#pragma unroll
        for (int k16 = 0; k16 < 8; ++k16) {
            uint32_t uxa = (uint32_t)(((2 * k16 + ua) ^ l7) << 4);
            uint32_t uxb = (uint32_t)(((2 * k16 + ub) ^ l7) << 4);

            uint32_t aH[2][4], bH[2][4];
#pragma unroll
            for (int mf = 0; mf < 2; ++mf)
                LDMATRIX_X4(aH[mf][0], aH[mf][1], aH[mf][2], aH[mf][3],
                            abase + arel[mf] + uxa);
#pragma unroll
            for (int nf2 = 0; nf2 < 2; ++nf2)
                LDMATRIX_X4(bH[nf2][0], bH[nf2][1], bH[nf2][2], bH[nf2][3],
                            brow[nf2] + uxb);

            // Term 1: Ah * Bh
#pragma unroll
            for (int mf = 0; mf < 2; ++mf)
#pragma unroll
                for (int nf = 0; nf < 4; ++nf)
                    MMA_BF16(acc[mf][nf], aH[mf][0], aH[mf][1], aH[mf][2], aH[mf][3],
                             bH[nf >> 1][(nf & 1) * 2], bH[nf >> 1][(nf & 1) * 2 + 1]);

            // Term 2: Ah * Bl
            {
                uint32_t bL[2][4];
#pragma unroll
                for (int nf2 = 0; nf2 < 2; ++nf2)
                    LDMATRIX_X4(bL[nf2][0], bL[nf2][1], bL[nf2][2], bL[nf2][3],
                                brow[nf2] + 32768u + uxb);
#pragma unroll
                for (int mf = 0; mf < 2; ++mf)
#pragma unroll
                    for (int nf = 0; nf < 4; ++nf)
                        MMA_BF16(acc[mf][nf], aH[mf][0], aH[mf][1], aH[mf][2], aH[mf][3],
                                 bL[nf >> 1][(nf & 1) * 2], bL[nf >> 1][(nf & 1) * 2 + 1]);
            }

            // Term 3: Al * Bh
            {
                uint32_t aL[2][4];
#pragma unroll
                for (int mf = 0; mf < 2; ++mf)
                    LDMATRIX_X4(aL[mf][0], aL[mf][1], aL[mf][2], aL[mf][3],
                                abase + 16384u + arel[mf] + uxa);
#pragma unroll
                for (int mf = 0; mf < 2; ++mf)
#pragma unroll
                    for (int nf = 0; nf < 4; ++nf)
                        MMA_BF16(acc[mf][nf], aL[mf][0], aL[mf][1], aL[mf][2], aL[mf][3],
                                 bH[nf >> 1][(nf & 1) * 2], bH[nf >> 1][(nf & 1) * 2 + 1]);
            }
        }

        // ---- epilogue: write into (B,S,V) layout ----
        {
            int mt = u & 15;
            bool fullT = (cur_nt != NTILES - 1);
            int m0 = mt * 128 + grp * 64;
            int cbase = cur_nt * 128 + wn * 32 + (lane & 3) * 2;
#pragma unroll
            for (int mf = 0; mf < 2; ++mf) {
                int rr = m0 + wm * 32 + mf * 16 + (lane >> 2);
#pragma unroll
                for (int half = 0; half < 2; ++half) {
                    int m = rr + half * 8;
                    float* orow = out + (size_t)(m & 7) * SS * VV + (size_t)(m >> 3) * VV;
#pragma unroll
                    for (int nf = 0; nf < 4; ++nf) {
                        int c = cbase + nf * 8;
                        float v0 = acc[mf][nf][half * 2 + 0];
                        float v1 = acc[mf][nf][half * 2 + 1];
                        if (fullT) {
                            orow[c]     = v0;
                            orow[c + 1] = v1;
                        } else {
                            if (c < VV)     orow[c]     = v0;
                            if (c + 1 < VV) orow[c + 1] = v1;
                        }
                    }
                }
            }
        }

        if (havenext && !samen) {
            // nt boundary: all warps (both groups) must be done with B
            __syncthreads();
            cur_nt = nxt >> 4;
            issue_B(sb, cur_nt, tid);
            issue_Ag(parity ? abuf0 : abuf1, nxt & 15, grp, gtid);
            CP_COMMIT();
            freshB = true;
        } else {
            GBAR(bar);   // group's A buffer safe to refill next iteration
        }
        parity ^= 1;
        u = nxt;
    }
}

// ---------------------------------------------------------------------------
extern "C" void kernel_launch(void* const* d_in, const int* in_sizes, int n_in,
                              void* d_out, int out_size) {
    const int*   input_ids = (const int*)  d_in[0];
    const float* emb       = (const float*)d_in[1];
    const float* layer_W   = (const float*)d_in[2];
    const float* layer_b   = (const float*)d_in[3];
    const float* layer_Wr  = (const float*)d_in[4];
    const float* layer_Wi  = (const float*)d_in[5];
    const float* out_w     = (const float*)d_in[6];
    float* out = (float*)d_out;

    const int smem_layers = (2 * RES + BB * DD + 2 * BB * NN + 2 * DD * 36) * sizeof(float);
    cudaFuncSetAttribute(k_layers,    cudaFuncAttributeMaxDynamicSharedMemorySize, smem_layers);
    cudaFuncSetAttribute(k_logits_wg, cudaFuncAttributeMaxDynamicSharedMemorySize, (int)SMEM_PIPE);

    k_pre<<<24 + SPLITW_BLOCKS, 128>>>(input_ids, emb, out, out_w);
    k_layers<<<SS, 256, smem_layers>>>(layer_W, layer_b, layer_Wr, layer_Wi);
    k_logits_wg<<<CHUNKS, 512, SMEM_PIPE>>>(out);
}

// round 17
// speedup vs baseline: 1.1784x; 1.0552x over previous
#include <cuda_runtime.h>
#include <cuda_bf16.h>
#include <math.h>
#include <stdint.h>

#define RES   4096
#define DD    128
#define NN    256
#define BB    8
#define SS    256
#define VV    50257
#define LL    2
#define WROWS 50304          // 393 * 128, padded vocab rows
#define NTILES 393
#define MTILES 16
#define UNITS  (NTILES * MTILES)   // 6288
#define CHUNKS 444                 // 148 * 3 -> exactly 3 waves
#define SPLITW_BLOCKS 1184
#define MM    (SS * BB)            // 2048 rows of X

// Constants matching the reference's fp32 casts of python doubles
#define PHIF   ((float)1.6180339887498948482045868343656381177203)
#define STEPF  ((float)(6.2831853071795864769252867665590 / 4096.0))
#define SCALEF ((float)(4096.0 / 6.2831853071795864769252867665590))

// Scratch (no allocation allowed)
__device__ float g_sin[RES];
__device__ float g_cos[RES];
__device__ float g_X[MM * DD];        // rows m = t*8 + b, 128 cols
__device__ float g_CS[MM * NN];       // 2MB phA->phB scratch
__device__ float g_SN[MM * NN];       // 2MB

// Pre-split bf16 hi/lo planes (row-major: row*128 bf16 = 256B rows)
__device__ __align__(16) __nv_bfloat16 g_Wh[WROWS * DD];
__device__ __align__(16) __nv_bfloat16 g_Wl[WROWS * DD];
__device__ __align__(16) __nv_bfloat16 g_Xh[MM * DD];
__device__ __align__(16) __nv_bfloat16 g_Xl[MM * DD];

// ===========================================================================
// Helpers
// ===========================================================================
__device__ __forceinline__ uint32_t smem_u32(const void* p) {
    uint32_t a;
    asm("{ .reg .u64 t; cvta.to.shared.u64 t, %1; cvt.u32.u64 %0, t; }"
        : "=r"(a) : "l"(p));
    return a;
}

__device__ __forceinline__ uint32_t pk(__nv_bfloat16 a, __nv_bfloat16 b) {
    uint16_t ua = *(uint16_t*)&a, ub = *(uint16_t*)&b;
    return (uint32_t)ua | ((uint32_t)ub << 16);
}

#define LDMATRIX_X4(r0, r1, r2, r3, addr)                                     \
    asm volatile("ldmatrix.sync.aligned.m8n8.x4.shared.b16 {%0,%1,%2,%3}, [%4];" \
        : "=r"(r0), "=r"(r1), "=r"(r2), "=r"(r3) : "r"(addr))

#define MMA_BF16(c, a0, a1, a2, a3, b0, b1)                                   \
    asm volatile("mma.sync.aligned.m16n8k16.row.col.f32.bf16.bf16.f32 "       \
        "{%0,%1,%2,%3}, {%4,%5,%6,%7}, {%8,%9}, {%0,%1,%2,%3};"               \
        : "+f"((c)[0]), "+f"((c)[1]), "+f"((c)[2]), "+f"((c)[3])              \
        : "r"(a0), "r"(a1), "r"(a2), "r"(a3), "r"(b0), "r"(b1))

#define CP_ASYNC16(smaddr, gptr)                                              \
    asm volatile("cp.async.cg.shared.global [%0], [%1], 16;"                  \
        :: "r"(smaddr), "l"(gptr))
#define CP_COMMIT() asm volatile("cp.async.commit_group;" ::: "memory")
#define CP_WAIT0()  asm volatile("cp.async.wait_group 0;" ::: "memory")
#define CP_WAIT1()  asm volatile("cp.async.wait_group 1;" ::: "memory")
#define GBAR(id)    asm volatile("bar.sync %0, 256;" :: "r"(id) : "memory")

// ---------------------------------------------------------------------------
// fp32 -> bf16 hi/lo split of a float4
// ---------------------------------------------------------------------------
__device__ __forceinline__ void split4(float4 v, uint2& hp, uint2& lp) {
    __nv_bfloat16 h0 = __float2bfloat16(v.x);
    __nv_bfloat16 h1 = __float2bfloat16(v.y);
    __nv_bfloat16 h2 = __float2bfloat16(v.z);
    __nv_bfloat16 h3 = __float2bfloat16(v.w);
    __nv_bfloat16 l0 = __float2bfloat16(v.x - __bfloat162float(h0));
    __nv_bfloat16 l1 = __float2bfloat16(v.y - __bfloat162float(h1));
    __nv_bfloat16 l2 = __float2bfloat16(v.z - __bfloat162float(h2));
    __nv_bfloat16 l3 = __float2bfloat16(v.w - __bfloat162float(h3));
    hp = make_uint2(pk(h0, h1), pk(h2, h3));
    lp = make_uint2(pk(l0, l1), pk(l2, l3));
}

// ---------------------------------------------------------------------------
// Kernel 1 (mega-prologue): blocks 0-7 = recurrence (local tables, with
// one-group-ahead emb prefetch); blocks 8-23 = write g_sin/g_cos; blocks
// 24+ = out_w split (runs on the SMs idle during the recurrence).
// ---------------------------------------------------------------------------
__global__ void k_pre(const int* __restrict__ ids,
                      const float* __restrict__ emb,
                      float* __restrict__ out,
                      const float* __restrict__ Wv) {
    __shared__ float s_sin[RES];
    __shared__ float s_cos[RES];
    __shared__ int   s_ids[SS];

    int bid = blockIdx.x;
    int d   = threadIdx.x;   // 128 threads

    if (bid >= 24) {
        // ---- out_w fp32 -> bf16 hi/lo split (strided fat blocks) ----
        int total = WROWS * 32;
        for (int f = (bid - 24) * 128 + d; f < total; f += SPLITW_BLOCKS * 128) {
            int r = f >> 5, kq = f & 31;
            float4 v = make_float4(0.f, 0.f, 0.f, 0.f);
            if (r < VV) v = ((const float4*)Wv)[(size_t)r * 32 + kq];
            uint2 hp, lp;
            split4(v, hp, lp);
            ((uint2*)g_Wh)[f] = hp;
            ((uint2*)g_Wl)[f] = lp;
        }
        return;
    }
    if (bid >= 8) {
        // ---- write global sin/cos tables for phA lookups ----
        int i0 = (bid - 8) * 256;
        for (int j = d; j < 256; j += 128) {
            int i = i0 + j;
            float a = __fmul_rn((float)i, STEPF);
            g_sin[i] = sinf(a);
            g_cos[i] = cosf(a);
        }
        return;
    }

    // ---- recurrence for batch row b = bid (bit-exact path) ----
    int b = bid;
    for (int i = d; i < RES; i += 128) {
        float a = __fmul_rn((float)i, STEPF);   // identical to table formula
        s_sin[i] = sinf(a);
        s_cos[i] = cosf(a);
    }
    for (int i = d; i < SS; i += 128) s_ids[i] = ids[b * SS + i];
    __syncthreads();

    float hr = 0.0f, hi = 0.0f;
    float wv[8], bv[8], wv2[8], bv2[8];

    // preload group 0
#pragma unroll
    for (int j = 0; j < 8; ++j) {
        const float* e = emb + (size_t)s_ids[j] * (2 * DD);
        wv[j] = e[d];
        bv[j] = e[DD + d];
    }

    for (int t0 = 0; t0 < SS; t0 += 8) {
        // prefetch next group while computing this one
        if (t0 + 8 < SS) {
#pragma unroll
            for (int j = 0; j < 8; ++j) {
                const float* e = emb + (size_t)s_ids[t0 + 8 + j] * (2 * DD);
                wv2[j] = e[d];
                bv2[j] = e[DD + d];
            }
        }
#pragma unroll
        for (int j = 0; j < 8; ++j) {
            int   t     = t0 + j;
            float tphi  = __fmul_rn((float)t, PHIF);
            float num   = __fadd_rn(hr, hi);
            float den   = __fadd_rn(1.0f, fabsf(wv[j]));
            float theta = __fadd_rn(__fadd_rn(__fdiv_rn(num, den), bv[j]), tphi);
            int   idx   = __float2int_rn(__fmul_rn(theta, SCALEF)) & (RES - 1);
            hi = s_sin[idx];
            hr = s_cos[idx];
            g_X[(size_t)t * (BB * DD) + b * DD + d] = __fadd_rn(hr, hi);
        }
#pragma unroll
        for (int j = 0; j < 8; ++j) { wv[j] = wv2[j]; bv[j] = bv2[j]; }
    }

    size_t base = (size_t)BB * SS * VV;
    out[base + b * DD + d]            = hr;  // h_real
    out[base + BB * DD + b * DD + d]  = hi;  // h_imag
}

// ---------------------------------------------------------------------------
// Kernel 2a (phA, per layer): TH = X @ W_l^T + bias + t*phi -> table lookups
// -> g_CS / g_SN. Tiles 64(M) x 64(N), 128 blocks, 256 threads, dyn smem 68KB.
// ---------------------------------------------------------------------------
__global__ void __launch_bounds__(256)
k_phA(const float* __restrict__ W, const float* __restrict__ bias, int layer) {
    extern __shared__ float smA[];
    float* Xs = smA;               // 64 x 132
    float* Ws = smA + 64 * 132;    // 64 x 132

    int tid = threadIdx.x;
    int m0  = (blockIdx.x >> 2) * 64;   // 32 m-tiles
    int n0  = (blockIdx.x & 3) * 64;    // 4 n-tiles

    const float4* X4 = (const float4*)g_X;
    const float4* W4 = (const float4*)(W + (size_t)layer * NN * DD);
#pragma unroll
    for (int i = 0; i < 8; ++i) {
        int f = tid + 256 * i;          // 0..2047
        int r = f >> 5, kq = f & 31;
        *(float4*)(Xs + r * 132 + kq * 4) = X4[(size_t)(m0 + r) * 32 + kq];
        *(float4*)(Ws + r * 132 + kq * 4) = W4[(size_t)(n0 + r) * 32 + kq];
    }
    __syncthreads();

    int tx = tid & 15, ty = tid >> 4;
    float acc[4][4];
#pragma unroll
    for (int i = 0; i < 4; ++i)
#pragma unroll
        for (int j = 0; j < 4; ++j) acc[i][j] = 0.0f;

#pragma unroll 4
    for (int kq = 0; kq < 32; ++kq) {
        float4 a4[4], b4[4];
#pragma unroll
        for (int i = 0; i < 4; ++i)
            a4[i] = *(const float4*)(Xs + (ty + 16 * i) * 132 + kq * 4);
#pragma unroll
        for (int j = 0; j < 4; ++j)
            b4[j] = *(const float4*)(Ws + (tx + 16 * j) * 132 + kq * 4);
#pragma unroll
        for (int i = 0; i < 4; ++i)
#pragma unroll
            for (int j = 0; j < 4; ++j)
                acc[i][j] += a4[i].x * b4[j].x + a4[i].y * b4[j].y
                           + a4[i].z * b4[j].z + a4[i].w * b4[j].w;
    }

#pragma unroll
    for (int i = 0; i < 4; ++i) {
        int m = m0 + ty + 16 * i;
        float tphi = __fmul_rn((float)(m >> 3), PHIF);
#pragma unroll
        for (int j = 0; j < 4; ++j) {
            int n = n0 + tx + 16 * j;
            float th  = acc[i][j] + bias[layer * NN + n] + tphi;
            int   idx = __float2int_rn(__fmul_rn(th, SCALEF)) & (RES - 1);
            g_SN[(size_t)m * NN + n] = g_sin[idx];
            g_CS[(size_t)m * NN + n] = g_cos[idx];
        }
    }
}

// ---------------------------------------------------------------------------
// Kernel 2b (phB, per layer): O = CS @ Wr^T + SN @ Wi^T; x += silu(O).
// Tiles 32(M) x 32(D), K chunked by 64; 256 blocks, 256 threads, ~35KB smem.
// layer==1 additionally writes the bf16 hi/lo X planes.
// ---------------------------------------------------------------------------
__global__ void __launch_bounds__(256)
k_phB(const float* __restrict__ Wr, const float* __restrict__ Wi, int layer) {
    __shared__ float CSs[32 * 68];
    __shared__ float SNs[32 * 68];
    __shared__ float WRs[32 * 68];
    __shared__ float WIs[32 * 68];

    int tid = threadIdx.x;
    int m0  = (blockIdx.x >> 2) * 32;   // 64 m-tiles
    int d0  = (blockIdx.x & 3) * 32;    // 4 d-tiles
    int tx  = tid & 15, ty = tid >> 4;

    const float4* CS4 = (const float4*)g_CS;
    const float4* SN4 = (const float4*)g_SN;
    const float4* WR4 = (const float4*)(Wr + (size_t)layer * DD * NN);
    const float4* WI4 = (const float4*)(Wi + (size_t)layer * DD * NN);

    float o[2][2];
    o[0][0] = o[0][1] = o[1][0] = o[1][1] = 0.0f;

    for (int k0 = 0; k0 < NN; k0 += 64) {
        int kb = k0 >> 2;   // float4 offset within row
#pragma unroll
        for (int i = 0; i < 2; ++i) {
            int f = tid + 256 * i;      // 0..511
            int r = f >> 4, kq = f & 15;
            *(float4*)(CSs + r * 68 + kq * 4) = CS4[(size_t)(m0 + r) * 64 + kb + kq];
            *(float4*)(SNs + r * 68 + kq * 4) = SN4[(size_t)(m0 + r) * 64 + kb + kq];
            *(float4*)(WRs + r * 68 + kq * 4) = WR4[(size_t)(d0 + r) * 64 + kb + kq];
            *(float4*)(WIs + r * 68 + kq * 4) = WI4[(size_t)(d0 + r) * 64 + kb + kq];
        }
        __syncthreads();

#pragma unroll 4
        for (int q = 0; q < 16; ++q) {
            float4 cs0 = *(const float4*)(CSs + ty * 68 + q * 4);
            float4 cs1 = *(const float4*)(CSs + (ty + 16) * 68 + q * 4);
            float4 sn0 = *(const float4*)(SNs + ty * 68 + q * 4);
            float4 sn1 = *(const float4*)(SNs + (ty + 16) * 68 + q * 4);
            float4 wr0 = *(const float4*)(WRs + tx * 68 + q * 4);
            float4 wr1 = *(const float4*)(WRs + (tx + 16) * 68 + q * 4);
            float4 wi0 = *(const float4*)(WIs + tx * 68 + q * 4);
            float4 wi1 = *(const float4*)(WIs + (tx + 16) * 68 + q * 4);
            o[0][0] += cs0.x*wr0.x + cs0.y*wr0.y + cs0.z*wr0.z + cs0.w*wr0.w
                     + sn0.x*wi0.x + sn0.y*wi0.y + sn0.z*wi0.z + sn0.w*wi0.w;
            o[0][1] += cs0.x*wr1.x + cs0.y*wr1.y + cs0.z*wr1.z + cs0.w*wr1.w
                     + sn0.x*wi1.x + sn0.y*wi1.y + sn0.z*wi1.z + sn0.w*wi1.w;
            o[1][0] += cs1.x*wr0.x + cs1.y*wr0.y + cs1.z*wr0.z + cs1.w*wr0.w
                     + sn1.x*wi0.x + sn1.y*wi0.y + sn1.z*wi0.z + sn1.w*wi0.w;
            o[1][1] += cs1.x*wr1.x + cs1.y*wr1.y + cs1.z*wr1.z + cs1.w*wr1.w
                     + sn1.x*wi1.x + sn1.y*wi1.y + sn1.z*wi1.z + sn1.w*wi1.w;
        }
        __syncthreads();
    }

#pragma unroll
    for (int p = 0; p < 2; ++p) {
        int m = m0 + ty + 16 * p;
#pragma unroll
        for (int r = 0; r < 2; ++r) {
            int dcol = d0 + tx + 16 * r;
            float ov = o[p][r];
            float sv = ov / (1.0f + expf(-ov));   // o * sigmoid(o)
            size_t gi = (size_t)m * DD + dcol;
            float xv = g_X[gi] + sv;
            g_X[gi] = xv;
            if (layer == LL - 1) {
                __nv_bfloat16 h = __float2bfloat16(xv);
                __nv_bfloat16 l = __float2bfloat16(xv - __bfloat162float(h));
                g_Xh[gi] = h;
                g_Xl[gi] = l;
            }
        }
    }
}

// ---------------------------------------------------------------------------
// Kernel 3: work-list logits GEMM with TWO independent 8-warp groups.
//   EXACT byte-identical copy of the 409.6us-measured version. Do not touch.
// smem: BH 32K | BL 32K | G0A0 32K | G0A1 32K | G1A0 32K | G1A1 32K = 192K
// ---------------------------------------------------------------------------
#define PB_BH 0u
#define PB_BL 32768u
#define PB_A  65536u
#define SMEM_PIPE 196608u

__device__ __forceinline__ void issue_B(uint32_t sb, int nt, int tid) {
    const char* gWh = (const char*)g_Wh;
    const char* gWl = (const char*)g_Wl;
#pragma unroll
    for (int i = 0; i < 4; ++i) {
        int f = tid + 512 * i;            // 0..2047
        int r = f >> 4, u = f & 15;
        uint32_t so = (uint32_t)(r * 256 + ((u ^ (r & 7)) << 4));
        size_t   go = (size_t)(nt * 128 + r) * 256 + u * 16;
        CP_ASYNC16(sb + PB_BH + so, gWh + go);
        CP_ASYNC16(sb + PB_BL + so, gWl + go);
    }
}

// Load 64 rows (this group's half of an M-tile) into a 32KB buffer.
__device__ __forceinline__ void issue_Ag(uint32_t abuf, int mt, int grp, int gtid) {
    const char* gXh = (const char*)g_Xh;
    const char* gXl = (const char*)g_Xl;
#pragma unroll
    for (int i = 0; i < 4; ++i) {
        int f = gtid + 256 * i;           // 0..1023
        int r = f >> 4, u = f & 15;       // r: 0..63
        uint32_t so = (uint32_t)(r * 256 + ((u ^ (r & 7)) << 4));
        size_t   go = (size_t)(mt * 128 + grp * 64 + r) * 256 + u * 16;
        CP_ASYNC16(abuf + so, gXh + go);
        CP_ASYNC16(abuf + 16384u + so, gXl + go);
    }
}

__global__ void __launch_bounds__(512, 1)
k_logits_wg(float* __restrict__ out) {
    extern __shared__ char smc[];
    uint32_t sb = smem_u32(smc);

    int tid  = threadIdx.x;
    int lane = tid & 31;
    int wid  = tid >> 5;
    int grp  = wid >> 3;           // 0 or 1
    int gwid = wid & 7;            // warp within group
    int gtid = tid & 255;
    int bar  = 1 + grp;
    int cid  = blockIdx.x;

    int start = (cid * UNITS) / CHUNKS;
    int end   = ((cid + 1) * UNITS) / CHUNKS;

    int wm = gwid & 1;             // M offset within 64-row half: 0/32
    int wn = gwid >> 1;            // N offset: 0/32/64/96
    int g  = lane >> 3;
    int l7 = lane & 7;
    int ra = l7 + (g & 1) * 8;
    int ua = g >> 1;
    int rb = l7 + (g >> 1) * 8;
    int ub = g & 1;

    // A buffer bases for this group (hi plane; lo at +16384)
    uint32_t abuf0 = sb + PB_A + (uint32_t)grp * 65536u;
    uint32_t abuf1 = abuf0 + 32768u;

    uint32_t arel[2];
#pragma unroll
    for (int mf = 0; mf < 2; ++mf)
        arel[mf] = (uint32_t)((wm * 32 + mf * 16 + ra) * 256);
    uint32_t brow[2];
#pragma unroll
    for (int nf2 = 0; nf2 < 2; ++nf2)
        brow[nf2] = sb + PB_BH + (uint32_t)((wn * 32 + nf2 * 16 + rb) * 256);

    int u = start;
    int cur_nt = u >> 4;
    issue_B(sb, cur_nt, tid);
    issue_Ag(abuf0, u & 15, grp, gtid);
    CP_COMMIT();
    int parity = 0;
    bool freshB = true;

    while (u < end) {
        int nxt = u + 1;
        bool havenext = (nxt < end);
        bool samen = havenext && ((nxt >> 4) == cur_nt);
        if (samen) {
            issue_Ag(parity ? abuf0 : abuf1, nxt & 15, grp, gtid);
            CP_COMMIT();
            CP_WAIT1();
        } else {
            CP_WAIT0();
        }
        if (freshB) { __syncthreads(); freshB = false; }
        else        { GBAR(bar); }

        uint32_t abase = parity ? abuf1 : abuf0;

        float acc[2][4][4];
#pragma unroll
        for (int i = 0; i < 2; ++i)
#pragma unroll
            for (int j = 0; j < 4; ++j)
#pragma unroll
                for (int q = 0; q < 4; ++q) acc[i][j][q] = 0.0f;

#pragma unroll
        for (int k16 = 0; k16 < 8; ++k16) {
            uint32_t uxa = (uint32_t)(((2 * k16 + ua) ^ l7) << 4);
            uint32_t uxb = (uint32_t)(((2 * k16 + ub) ^ l7) << 4);

            uint32_t aH[2][4], bH[2][4];
#pragma unroll
            for (int mf = 0; mf < 2; ++mf)
                LDMATRIX_X4(aH[mf][0], aH[mf][1], aH[mf][2], aH[mf][3],
                            abase + arel[mf] + uxa);
#pragma unroll
            for (int nf2 = 0; nf2 < 2; ++nf2)
                LDMATRIX_X4(bH[nf2][0], bH[nf2][1], bH[nf2][2], bH[nf2][3],
                            brow[nf2] + uxb);

            // Term 1: Ah * Bh
#pragma unroll
            for (int mf = 0; mf < 2; ++mf)
#pragma unroll
                for (int nf = 0; nf < 4; ++nf)
                    MMA_BF16(acc[mf][nf], aH[mf][0], aH[mf][1], aH[mf][2], aH[mf][3],
                             bH[nf >> 1][(nf & 1) * 2], bH[nf >> 1][(nf & 1) * 2 + 1]);

            // Term 2: Ah * Bl
            {
                uint32_t bL[2][4];
#pragma unroll
                for (int nf2 = 0; nf2 < 2; ++nf2)
                    LDMATRIX_X4(bL[nf2][0], bL[nf2][1], bL[nf2][2], bL[nf2][3],
                                brow[nf2] + 32768u + uxb);
#pragma unroll
                for (int mf = 0; mf < 2; ++mf)
#pragma unroll
                    for (int nf = 0; nf < 4; ++nf)
                        MMA_BF16(acc[mf][nf], aH[mf][0], aH[mf][1], aH[mf][2], aH[mf][3],
                                 bL[nf >> 1][(nf & 1) * 2], bL[nf >> 1][(nf & 1) * 2 + 1]);
            }

            // Term 3: Al * Bh
            {
                uint32_t aL[2][4];
#pragma unroll
                for (int mf = 0; mf < 2; ++mf)
                    LDMATRIX_X4(aL[mf][0], aL[mf][1], aL[mf][2], aL[mf][3],
                                abase + 16384u + arel[mf] + uxa);
#pragma unroll
                for (int mf = 0; mf < 2; ++mf)
#pragma unroll
                    for (int nf = 0; nf < 4; ++nf)
                        MMA_BF16(acc[mf][nf], aL[mf][0], aL[mf][1], aL[mf][2], aL[mf][3],
                                 bH[nf >> 1][(nf & 1) * 2], bH[nf >> 1][(nf & 1) * 2 + 1]);
            }
        }

        // ---- epilogue: write into (B,S,V) layout ----
        {
            int mt = u & 15;
            bool fullT = (cur_nt != NTILES - 1);
            int m0 = mt * 128 + grp * 64;
            int cbase = cur_nt * 128 + wn * 32 + (lane & 3) * 2;
#pragma unroll
            for (int mf = 0; mf < 2; ++mf) {
                int rr = m0 + wm * 32 + mf * 16 + (lane >> 2);
#pragma unroll
                for (int half = 0; half < 2; ++half) {
                    int m = rr + half * 8;
                    float* orow = out + (size_t)(m & 7) * SS * VV + (size_t)(m >> 3) * VV;
#pragma unroll
                    for (int nf = 0; nf < 4; ++nf) {
                        int c = cbase + nf * 8;
                        float v0 = acc[mf][nf][half * 2 + 0];
                        float v1 = acc[mf][nf][half * 2 + 1];
                        if (fullT) {
                            orow[c]     = v0;
                            orow[c + 1] = v1;
                        } else {
                            if (c < VV)     orow[c]     = v0;
                            if (c + 1 < VV) orow[c + 1] = v1;
                        }
                    }
                }
            }
        }

        if (havenext && !samen) {
            // nt boundary: all warps (both groups) must be done with B
            __syncthreads();
            cur_nt = nxt >> 4;
            issue_B(sb, cur_nt, tid);
            issue_Ag(parity ? abuf0 : abuf1, nxt & 15, grp, gtid);
            CP_COMMIT();
            freshB = true;
        } else {
            GBAR(bar);   // group's A buffer safe to refill next iteration
        }
        parity ^= 1;
        u = nxt;
    }
}

// ---------------------------------------------------------------------------
extern "C" void kernel_launch(void* const* d_in, const int* in_sizes, int n_in,
                              void* d_out, int out_size) {
    const int*   input_ids = (const int*)  d_in[0];
    const float* emb       = (const float*)d_in[1];
    const float* layer_W   = (const float*)d_in[2];
    const float* layer_b   = (const float*)d_in[3];
    const float* layer_Wr  = (const float*)d_in[4];
    const float* layer_Wi  = (const float*)d_in[5];
    const float* out_w     = (const float*)d_in[6];
    float* out = (float*)d_out;

    const int smem_phA = 2 * 64 * 132 * sizeof(float);   // 67.5KB
    cudaFuncSetAttribute(k_phA,       cudaFuncAttributeMaxDynamicSharedMemorySize, smem_phA);
    cudaFuncSetAttribute(k_logits_wg, cudaFuncAttributeMaxDynamicSharedMemorySize, (int)SMEM_PIPE);

    k_pre<<<24 + SPLITW_BLOCKS, 128>>>(input_ids, emb, out, out_w);
    for (int l = 0; l < LL; ++l) {
        k_phA<<<128, 256, smem_phA>>>(layer_W, layer_b, l);
        k_phB<<<256, 256>>>(layer_Wr, layer_Wi, l);
    }
    k_logits_wg<<<CHUNKS, 512, SMEM_PIPE>>>(out);
}